// round 13
// baseline (speedup 1.0000x reference)
#include <cuda_runtime.h>
#include <cuda_fp16.h>
#include <cstdint>

typedef __half fp16;

// ---------------- problem constants ----------------
#define DD 512
#define MAXB 32768
#define NSPLIT 16
#define BKT 64                          // K per stage -> 128B rows
#define MT 256
#define NT 128
#define TILE_A (MT * BKT * 2)           // 32768 B (A tile)
#define TILE_BB (NT * BKT * 2)          // 16384 B (B tile)
#define STAGE_B (TILE_A + TILE_BB)      // 49152 B
#define SMEM_DYN (2 * STAGE_B + 128)    // 98432 B -> 1 CTA/SM (512 thr)

// ---------------- scratch (device globals; no allocation) ----------------
__device__ __align__(256) fp16 g_s_hi[(size_t)MAXB * DD];
__device__ __align__(256) fp16 g_p_hi[(size_t)MAXB * DD];
__device__ __align__(256) fp16 g_st_hi[(size_t)DD * MAXB];
__device__ __align__(256) fp16 g_pt_hi[(size_t)DD * MAXB];
__device__ __align__(256) fp16 g_wt_hi[DD * DD];
__device__ __align__(256) fp16 g_wrt_hi[DD * DD];
__device__ __align__(256) float g_stim_out[(size_t)MAXB * DD];
__device__ __align__(256) float g_rec_out[(size_t)MAXB * DD];
__device__ __align__(256) float g_partS[(size_t)NSPLIT * DD * DD];
__device__ __align__(256) float g_partP[(size_t)NSPLIT * DD * DD];

// ---------------- PTX helpers (base-ISA only: sm_80+ safe) ----------------
__device__ __forceinline__ uint32_t smem_u32(const void* p) {
    uint32_t a;
    asm("{ .reg .u64 t; cvta.to.shared.u64 t, %1; cvt.u32.u64 %0, t; }" : "=r"(a) : "l"(p));
    return a;
}
__device__ __forceinline__ void ldsm_x4(uint32_t* r, uint32_t addr) {
    asm volatile("ldmatrix.sync.aligned.m8n8.x4.shared.b16 {%0,%1,%2,%3}, [%4];"
                 : "=r"(r[0]), "=r"(r[1]), "=r"(r[2]), "=r"(r[3]) : "r"(addr));
}
__device__ __forceinline__ void mma16816(float* c, const uint32_t* a, uint32_t b0, uint32_t b1) {
    asm volatile(
        "mma.sync.aligned.m16n8k16.row.col.f32.f16.f16.f32 "
        "{%0,%1,%2,%3}, {%4,%5,%6,%7}, {%8,%9}, {%0,%1,%2,%3};"
        : "+f"(c[0]), "+f"(c[1]), "+f"(c[2]), "+f"(c[3])
        : "r"(a[0]), "r"(a[1]), "r"(a[2]), "r"(a[3]), "r"(b0), "r"(b1));
}
__device__ __forceinline__ void cp16(uint32_t dst, const void* src) {
    asm volatile("cp.async.cg.shared.global [%0], [%1], 16;" :: "r"(dst), "l"(src) : "memory");
}
#define CP_COMMIT() asm volatile("cp.async.commit_group;" ::: "memory")

// swizzled smem byte offset within a tile: 128B rows, 8 x 16B chunks, chunk xor (row&7)
__device__ __forceinline__ uint32_t swz(int row, int chunk) {
    return (uint32_t)(row * 128 + ((chunk ^ (row & 7)) << 4));
}

__device__ __forceinline__ uint32_t pack2h(fp16 a, fp16 b) {
    return (uint32_t)__half_as_ushort(a) | ((uint32_t)__half_as_ushort(b) << 16);
}

// ---------------- segment descriptor for the merged GEMM launch ----------------
struct Seg {
    const fp16 *Ah, *Bh;
    int lda, ldb;
    float* C;
    int pstride;
    int kc;     // K per block
    int gram;   // 0: forward tiling, 1: partial-coverage gram tiling
    int blk0;   // first global block id of this segment
};
struct Seg4 { Seg s[4]; };

// ---------------- merged single-pass fp16 GEMM: all 4 GEMMs in one launch ----------------
// C = A @ B^T, fp16 inputs, fp32 accumulate. 256x128 CTA tile, 512 threads,
// warp tile 32x64 (16 warps as 8x2), double-buffered cp.async, 1 CTA/SM.
__global__ __launch_bounds__(512, 1)
void mma_all(Seg4 segs) {
    extern __shared__ char smraw[];
    const uint32_t base = (smem_u32(smraw) + 127u) & ~127u;

    const int bid = blockIdx.x;
    int si = (bid >= segs.s[2].blk0) ? ((bid >= segs.s[3].blk0) ? 3 : 2)
                                     : ((bid >= segs.s[1].blk0) ? 1 : 0);
    const Seg sg = segs.s[si];
    const int b = bid - sg.blk0;

    const int tid = threadIdx.x;
    const int lane = tid & 31;
    const int wid = tid >> 5;       // 0..15
    const int wm = wid >> 1;        // 8 warp-rows of 32
    const int wn = wid & 1;         // 2 warp-cols of 64
    const int r15 = lane & 15;
    const int hi4 = lane >> 4;

    int m0, n0, kbase;
    float* C = sg.C;
    if (sg.gram) {
        // 6 tiles of 256x128 covering all of G up to symmetry:
        // rows{0,1}x all cols, rows{2,3}x cols{2,3}  (128-blocks)
        const int GI[6] = {0, 0, 0, 0, 1, 1};
        const int GJ[6] = {0, 1, 2, 3, 2, 3};
        int p = b % 6, z = b / 6;
        m0 = GI[p] * MT;
        n0 = GJ[p] * NT;
        kbase = z * sg.kc;
        C += (long)z * sg.pstride;
    } else {
        m0 = (b >> 2) * MT;
        n0 = (b & 3) * NT;
        kbase = 0;
    }
    const int niter = sg.kc / BKT;

    // ---- hoisted loader state ----
    const int rr = tid >> 3;                 // 0..63 base row
    const int cch = tid & 7;                 // chunk index
    const uint32_t dA = (uint32_t)(rr * 128 + ((cch ^ (rr & 7)) << 4));
    const int offA = 64 * sg.lda;            // per-q source row step (elements)
    const int offB = 64 * sg.ldb;
    const fp16* pAh = sg.Ah + (m0 + rr) * sg.lda + cch * 8 + kbase;
    const fp16* pBh = sg.Bh + (n0 + rr) * sg.ldb + cch * 8 + kbase;

#define LOAD_STAGE(sbase) do {                                                  \
    const uint32_t d0 = (sbase) + dA;                                           \
    _Pragma("unroll") for (int q = 0; q < 4; ++q)                               \
        cp16(d0 + q * 8192, pAh + q * offA);                                    \
    _Pragma("unroll") for (int q = 0; q < 2; ++q)                               \
        cp16(d0 + TILE_A + q * 8192, pBh + q * offB);                           \
    CP_COMMIT();                                                                \
    pAh += BKT; pBh += BKT;                                                     \
} while (0)

    float acc[2][8][4];
#pragma unroll
    for (int i = 0; i < 2; ++i)
#pragma unroll
        for (int j = 0; j < 8; ++j)
#pragma unroll
            for (int q = 0; q < 4; ++q) acc[i][j][q] = 0.f;

    // prologue: stage 0
    LOAD_STAGE(base);

    for (int i = 0; i < niter; ++i) {
        asm volatile("cp.async.wait_group 0;" ::: "memory");
        __syncthreads();

        if (i + 1 < niter)
            LOAD_STAGE(base + ((i + 1) & 1) * STAGE_B);

        const uint32_t sb = base + (i & 1) * STAGE_B;
        const uint32_t Ah = sb, Bh = sb + TILE_A;

#pragma unroll
        for (int ks = 0; ks < 4; ++ks) {
            uint32_t ah[2][4], bh[4][4];
            int ck = 2 * ks + hi4;
#pragma unroll
            for (int mt = 0; mt < 2; ++mt) {
                int row = wm * 32 + mt * 16 + r15;
                ldsm_x4(ah[mt], Ah + swz(row, ck));
            }
#pragma unroll
            for (int np = 0; np < 4; ++np) {
                int row = wn * 64 + np * 16 + r15;
                ldsm_x4(bh[np], Bh + swz(row, ck));
            }
#pragma unroll
            for (int mt = 0; mt < 2; ++mt)
#pragma unroll
                for (int nt = 0; nt < 8; ++nt) {
                    int np = nt >> 1, p = nt & 1;
                    mma16816(acc[mt][nt], ah[mt], bh[np][p], bh[np][p + 2]);
                }
        }
    }

    // epilogue: write fp32 directly from accumulators
#pragma unroll
    for (int mt = 0; mt < 2; ++mt) {
        int row = m0 + wm * 32 + mt * 16 + (lane >> 2);
#pragma unroll
        for (int nt = 0; nt < 8; ++nt) {
            int col = n0 + wn * 64 + nt * 8 + 2 * (lane & 3);
            *(float2*)&C[(long)row * DD + col] = make_float2(acc[mt][nt][0], acc[mt][nt][1]);
            *(float2*)&C[(long)(row + 8) * DD + col] = make_float2(acc[mt][nt][2], acc[mt][nt][3]);
        }
    }
#undef LOAD_STAGE
}

// ------- prep: coalesced fp16 quantize, row-major + transposed, packed stores -------
__global__ __launch_bounds__(256) void prep_big(const float* __restrict__ X,
                                                uint32_t* __restrict__ Hr,
                                                uint32_t* __restrict__ Th,
                                                int R, int C) {
    __shared__ float s[64][65];
    const int tid = threadIdx.x;
    const int c0 = blockIdx.x * 64, r0 = blockIdx.y * 64;

#pragma unroll
    for (int k = 0; k < 8; ++k) {
        int u = tid + k * 256;
        int rl = u >> 5, c2 = (u & 31) * 2;
        long ga = (long)(r0 + rl) * C + c0 + c2;
        float2 v = *(const float2*)&X[ga];
        Hr[ga >> 1] = pack2h(__float2half(v.x), __float2half(v.y));
        s[c2][rl] = v.x;
        s[c2 + 1][rl] = v.y;
    }
    __syncthreads();
#pragma unroll
    for (int k = 0; k < 8; ++k) {
        int u = tid + k * 256;
        int fl = u >> 5, r2 = (u & 31) * 2;
        long ta = (long)(c0 + fl) * R + r0 + r2;
        Th[ta >> 1] = pack2h(__float2half(s[fl][r2]), __float2half(s[fl][r2 + 1]));
    }
}

// ------- prep for weights: transposed fp16 quantize, W and Wr via grid.z -------
__global__ __launch_bounds__(256) void prep_w(const float* __restrict__ W0,
                                              const float* __restrict__ W1,
                                              uint32_t* __restrict__ T0h,
                                              uint32_t* __restrict__ T1h) {
    __shared__ float s[64][65];
    const int tid = threadIdx.x;
    const int c0 = blockIdx.x * 64, r0 = blockIdx.y * 64;
    const float* X = blockIdx.z ? W1 : W0;
    uint32_t* Th = blockIdx.z ? T1h : T0h;

#pragma unroll
    for (int k = 0; k < 8; ++k) {
        int u = tid + k * 256;
        int rl = u >> 5, c2 = (u & 31) * 2;
        float2 v = *(const float2*)&X[(long)(r0 + rl) * DD + c0 + c2];
        s[c2][rl] = v.x;
        s[c2 + 1][rl] = v.y;
    }
    __syncthreads();
#pragma unroll
    for (int k = 0; k < 8; ++k) {
        int u = tid + k * 256;
        int fl = u >> 5, r2 = (u & 31) * 2;
        long ta = (long)(c0 + fl) * DD + r0 + r2;
        Th[ta >> 1] = pack2h(__float2half(s[fl][r2]), __float2half(s[fl][r2 + 1]));
    }
}

// ---------------- warp-per-row fused LN(rec) -> add stim -> relu -> LN(act) ----------------
__global__ __launch_bounds__(256) void ln_fuse(const float* __restrict__ rec,
                                               const float* __restrict__ stim,
                                               const float* __restrict__ grec,
                                               const float* __restrict__ brec,
                                               const float* __restrict__ gact,
                                               const float* __restrict__ bact,
                                               float* __restrict__ out) {
    const int lane = threadIdx.x & 31;
    const long row = (long)blockIdx.x * 8 + (threadIdx.x >> 5);
    const float* rr = rec + row * DD;
    const float* sr = stim + row * DD;
    float* orow = out + row * DD;

    float x[16];
    float a = 0.f, bsum = 0.f;
#pragma unroll
    for (int e = 0; e < 16; ++e) {
        x[e] = rr[e * 32 + lane];
        a += x[e];
        bsum += x[e] * x[e];
    }
#pragma unroll
    for (int o = 16; o; o >>= 1) {
        a += __shfl_xor_sync(0xffffffffu, a, o);
        bsum += __shfl_xor_sync(0xffffffffu, bsum, o);
    }
    float mu = a * (1.f / DD);
    float var = bsum * (1.f / DD) - mu * mu;
    float rstd = rsqrtf(var + 1e-5f);

    float v[16];
    a = 0.f; bsum = 0.f;
#pragma unroll
    for (int e = 0; e < 16; ++e) {
        int c = e * 32 + lane;
        float rn = (x[e] - mu) * rstd * grec[c] + brec[c];
        v[e] = fmaxf(sr[c] + rn, 0.f);
        a += v[e];
        bsum += v[e] * v[e];
    }
#pragma unroll
    for (int o = 16; o; o >>= 1) {
        a += __shfl_xor_sync(0xffffffffu, a, o);
        bsum += __shfl_xor_sync(0xffffffffu, bsum, o);
    }
    float mu2 = a * (1.f / DD);
    float var2 = bsum * (1.f / DD) - mu2 * mu2;
    float rstd2 = rsqrtf(var2 + 1e-5f);
#pragma unroll
    for (int e = 0; e < 16; ++e) {
        int c = e * 32 + lane;
        orow[c] = (v[e] - mu2) * rstd2 * gact[c] + bact[c];
    }
}

// ---- weight update (fused gram reduction + symmetric mirror):
//      G = sum_z part[z] (mirrored), out = l2norm_rows(W*(1-decay_i) + alpha_j*(G@W)) ----
#define RPC 8
__global__ __launch_bounds__(512) void weight_update(const float* __restrict__ W0,
                                                     const float* __restrict__ partS,
                                                     const float* __restrict__ W1,
                                                     const float* __restrict__ partP,
                                                     const float* __restrict__ alpha,
                                                     const float* __restrict__ decay,
                                                     float* __restrict__ out0,
                                                     float* __restrict__ out1) {
    const float* Wm = blockIdx.y ? W1 : W0;
    const float* part = blockIdx.y ? partP : partS;
    float* outp = blockIdx.y ? out1 : out0;

    const int i0 = blockIdx.x * RPC;
    const int j = threadIdx.x;
    const int lane = j & 31;
    const int w = j >> 5;

    __shared__ float Gsm[RPC][DD];
    __shared__ float red[16];
    __shared__ float norms[RPC];

    // gram reduction with mirror: computed blocks are rows{0,1}x all, rows{2,3}x cols{2,3}
#pragma unroll
    for (int r = 0; r < RPC; ++r) {
        int i = i0 + r;
        size_t src = (i < 256 || j >= 256) ? ((size_t)i * DD + j) : ((size_t)j * DD + i);
        float s = 0.f;
#pragma unroll
        for (int z = 0; z < NSPLIT; ++z) s += part[(size_t)z * DD * DD + src];
        Gsm[r][j] = s;
    }
    __syncthreads();

    float acc[RPC];
#pragma unroll
    for (int r = 0; r < RPC; ++r) acc[r] = 0.f;

#pragma unroll 4
    for (int k = 0; k < DD; ++k) {
        float wv = Wm[(size_t)k * DD + j];
#pragma unroll
        for (int r = 0; r < RPC; ++r) acc[r] = fmaf(Gsm[r][k], wv, acc[r]);
    }

    float aj = alpha[j];
#pragma unroll
    for (int r = 0; r < RPC; ++r)
        acc[r] = Wm[(size_t)(i0 + r) * DD + j] * (1.f - decay[i0 + r]) + aj * acc[r];

    for (int r = 0; r < RPC; ++r) {
        float s = acc[r] * acc[r];
#pragma unroll
        for (int o = 16; o; o >>= 1) s += __shfl_xor_sync(0xffffffffu, s, o);
        if (lane == 0) red[w] = s;
        __syncthreads();
        if (j == 0) {
            float tsum = 0.f;
#pragma unroll
            for (int q = 0; q < 16; ++q) tsum += red[q];
            norms[r] = fmaxf(sqrtf(tsum), 1e-12f);
        }
        __syncthreads();
    }

#pragma unroll
    for (int r = 0; r < RPC; ++r)
        outp[(size_t)(i0 + r) * DD + j] = acc[r] / norms[r];
}

// ---------------- launch ----------------
extern "C" void kernel_launch(void* const* d_in, const int* in_sizes, int n_in,
                              void* d_out, int out_size) {
    const float* stim = (const float*)d_in[0];
    const float* prev = (const float*)d_in[1];
    const float* W    = (const float*)d_in[2];
    const float* Wr   = (const float*)d_in[3];
    const float* alpha = (const float*)d_in[4];
    const float* decay = (const float*)d_in[5];
    const float* gact = (const float*)d_in[6];
    const float* bact = (const float*)d_in[7];
    const float* grec = (const float*)d_in[8];
    const float* brec = (const float*)d_in[9];
    float* out = (float*)d_out;

    const int Brows = in_sizes[0] / DD;  // 32768

    fp16 *s_hi, *p_hi, *st_hi, *pt_hi, *wt_hi, *wrt_hi;
    float *stim_out, *rec_out, *partS, *partP;
    cudaGetSymbolAddress((void**)&s_hi, g_s_hi);
    cudaGetSymbolAddress((void**)&p_hi, g_p_hi);
    cudaGetSymbolAddress((void**)&st_hi, g_st_hi);
    cudaGetSymbolAddress((void**)&pt_hi, g_pt_hi);
    cudaGetSymbolAddress((void**)&wt_hi, g_wt_hi);
    cudaGetSymbolAddress((void**)&wrt_hi, g_wrt_hi);
    cudaGetSymbolAddress((void**)&stim_out, g_stim_out);
    cudaGetSymbolAddress((void**)&rec_out, g_rec_out);
    cudaGetSymbolAddress((void**)&partS, g_partS);
    cudaGetSymbolAddress((void**)&partP, g_partP);

    cudaFuncSetAttribute(mma_all, cudaFuncAttributeMaxDynamicSharedMemorySize, SMEM_DYN);

    // launches 0-2: prep (mma_all stays at ncu capture index 3)
    prep_big<<<dim3(DD / 64, Brows / 64), 256>>>(stim, (uint32_t*)s_hi, (uint32_t*)st_hi, Brows, DD);
    prep_big<<<dim3(DD / 64, Brows / 64), 256>>>(prev, (uint32_t*)p_hi, (uint32_t*)pt_hi, Brows, DD);
    prep_w<<<dim3(DD / 64, DD / 64, 2), 256>>>(W, Wr, (uint32_t*)wt_hi, (uint32_t*)wrt_hi);

    // launch 3: ALL four GEMMs merged, gram blocks first (LPT order)
    const int fwdBlocks = (Brows / MT) * (DD / NT);   // 128*4 = 512
    const int gramBlocks = 6 * NSPLIT;                // 96
    const int kcg = Brows / NSPLIT;                   // 2048
    Seg4 segs;
    segs.s[0] = {st_hi, st_hi, Brows, Brows, partS, DD * DD, kcg, 1, 0};
    segs.s[1] = {pt_hi, pt_hi, Brows, Brows, partP, DD * DD, kcg, 1, gramBlocks};
    segs.s[2] = {s_hi, wt_hi, DD, DD, stim_out, 0, DD, 0, 2 * gramBlocks};
    segs.s[3] = {p_hi, wrt_hi, DD, DD, rec_out, 0, DD, 0, 2 * gramBlocks + fwdBlocks};
    mma_all<<<2 * gramBlocks + 2 * fwdBlocks, 512, SMEM_DYN>>>(segs);

    ln_fuse<<<(unsigned)(Brows / 8), 256>>>(rec_out, stim_out, grec, brec, gact, bact, out);

    size_t off = (size_t)Brows * DD;
    weight_update<<<dim3(DD / RPC, 2), 512>>>(W, partS, Wr, partP, alpha, decay,
                                              out + off, out + off + (size_t)DD * DD);
}

// round 14
// speedup vs baseline: 1.1355x; 1.1355x over previous
#include <cuda_runtime.h>
#include <cuda_fp16.h>
#include <cstdint>

typedef __half fp16;

// ---------------- problem constants ----------------
#define DD 512
#define MAXB 32768
#define NSPLIT 8
#define BKT 64                          // K per stage -> 128B rows
#define MT 128
#define NT 128
#define TILE_A (MT * BKT * 2)           // 16384 B per operand tile
#define STAGE_B (2 * TILE_A)            // 32768 B (A, B)
#define NSTAGE 3
#define SMEM_DYN (NSTAGE * STAGE_B + 128)   // 98432 B -> 2 CTAs/SM

// ---------------- scratch (device globals; no allocation) ----------------
__device__ __align__(256) fp16 g_s_hi[(size_t)MAXB * DD];
__device__ __align__(256) fp16 g_p_hi[(size_t)MAXB * DD];
__device__ __align__(256) fp16 g_st_hi[(size_t)DD * MAXB];
__device__ __align__(256) fp16 g_pt_hi[(size_t)DD * MAXB];
__device__ __align__(256) fp16 g_wt_hi[DD * DD];
__device__ __align__(256) fp16 g_wrt_hi[DD * DD];
__device__ __align__(256) fp16 g_stim_out[(size_t)MAXB * DD];
__device__ __align__(256) fp16 g_rec_out[(size_t)MAXB * DD];
__device__ __align__(256) float g_partS[(size_t)NSPLIT * DD * DD];
__device__ __align__(256) float g_partP[(size_t)NSPLIT * DD * DD];

// ---------------- PTX helpers (base-ISA only: sm_80+ safe) ----------------
__device__ __forceinline__ uint32_t smem_u32(const void* p) {
    uint32_t a;
    asm("{ .reg .u64 t; cvta.to.shared.u64 t, %1; cvt.u32.u64 %0, t; }" : "=r"(a) : "l"(p));
    return a;
}
__device__ __forceinline__ void ldsm_x4(uint32_t* r, uint32_t addr) {
    asm volatile("ldmatrix.sync.aligned.m8n8.x4.shared.b16 {%0,%1,%2,%3}, [%4];"
                 : "=r"(r[0]), "=r"(r[1]), "=r"(r[2]), "=r"(r[3]) : "r"(addr));
}
__device__ __forceinline__ void mma16816(float* c, const uint32_t* a, uint32_t b0, uint32_t b1) {
    asm volatile(
        "mma.sync.aligned.m16n8k16.row.col.f32.f16.f16.f32 "
        "{%0,%1,%2,%3}, {%4,%5,%6,%7}, {%8,%9}, {%0,%1,%2,%3};"
        : "+f"(c[0]), "+f"(c[1]), "+f"(c[2]), "+f"(c[3])
        : "r"(a[0]), "r"(a[1]), "r"(a[2]), "r"(a[3]), "r"(b0), "r"(b1));
}
__device__ __forceinline__ void cp16(uint32_t dst, const void* src) {
    asm volatile("cp.async.cg.shared.global [%0], [%1], 16;" :: "r"(dst), "l"(src) : "memory");
}
#define CP_COMMIT() asm volatile("cp.async.commit_group;" ::: "memory")

// swizzled smem byte offset within a tile: 128B rows, 8 x 16B chunks, chunk xor (row&7)
__device__ __forceinline__ uint32_t swz(int row, int chunk) {
    return (uint32_t)(row * 128 + ((chunk ^ (row & 7)) << 4));
}

__device__ __forceinline__ uint32_t pack2h(fp16 a, fp16 b) {
    return (uint32_t)__half_as_ushort(a) | ((uint32_t)__half_as_ushort(b) << 16);
}
__device__ __forceinline__ uint32_t pack2f(float a, float b) {
    return pack2h(__float2half(a), __float2half(b));
}

// ---------------- segment descriptor for the merged GEMM launch ----------------
struct Seg {
    const fp16 *Ah, *Bh;
    int lda, ldb;
    void* C;     // float* for gram partials, fp16* for forward outputs
    int pstride;
    int kc;      // K per block
    int gram;    // 0: forward tiling (fp16 out), 1: partial gram tiling (fp32 out)
    int blk0;
};
struct Seg4 { Seg s[4]; };

// ---------------- merged single-pass fp16 GEMM: all 4 GEMMs in one launch ----------------
// C = A @ B^T, fp16 inputs, fp32 accumulate. 128x128 CTA tile, warp tile 32x64,
// 3-stage cp.async pipeline, 2 CTAs/SM.  (R12 config — proven fastest.)
__global__ __launch_bounds__(256, 2)
void mma_all(Seg4 segs) {
    extern __shared__ char smraw[];
    const uint32_t base = (smem_u32(smraw) + 127u) & ~127u;

    const int bid = blockIdx.x;
    int si = (bid >= segs.s[2].blk0) ? ((bid >= segs.s[3].blk0) ? 3 : 2)
                                     : ((bid >= segs.s[1].blk0) ? 1 : 0);
    const Seg sg = segs.s[si];
    const int b = bid - sg.blk0;

    const int tid = threadIdx.x;
    const int lane = tid & 31;
    const int wid = tid >> 5;
    const int wm = wid >> 1;       // 4 warp-rows of 32
    const int wn = wid & 1;        // 2 warp-cols of 64
    const int r15 = lane & 15;
    const int hi4 = lane >> 4;

    int m0, n0, kbase, zoff = 0;
    if (sg.gram) {
        const int PI[10] = {0, 0, 0, 0, 1, 1, 1, 2, 2, 3};
        const int PJ[10] = {0, 1, 2, 3, 1, 2, 3, 2, 3, 3};
        int p = b % 10, z = b / 10;
        m0 = PI[p] * MT;
        n0 = PJ[p] * NT;
        kbase = z * sg.kc;
        zoff = z;
    } else {
        m0 = (b >> 2) * MT;
        n0 = (b & 3) * NT;
        kbase = 0;
    }
    const int niter = sg.kc / BKT;

    // ---- hoisted loader state ----
    const int rr = tid >> 3;                 // 0..31 base row
    const int cch = tid & 7;                 // chunk index
    const uint32_t dA = (uint32_t)(rr * 128 + ((cch ^ (rr & 7)) << 4));
    const int offA = 32 * sg.lda;
    const int offB = 32 * sg.ldb;
    const fp16* pAh = sg.Ah + (m0 + rr) * sg.lda + cch * 8 + kbase;
    const fp16* pBh = sg.Bh + (n0 + rr) * sg.ldb + cch * 8 + kbase;

#define LOAD_STAGE(sbase) do {                                                  \
    const uint32_t d0 = (sbase) + dA;                                           \
    _Pragma("unroll") for (int q = 0; q < 4; ++q)                               \
        cp16(d0 + q * 4096, pAh + q * offA);                                    \
    _Pragma("unroll") for (int q = 0; q < 4; ++q)                               \
        cp16(d0 + TILE_A + q * 4096, pBh + q * offB);                           \
    CP_COMMIT();                                                                \
    pAh += BKT; pBh += BKT;                                                     \
} while (0)

    float acc[2][8][4];
#pragma unroll
    for (int i = 0; i < 2; ++i)
#pragma unroll
        for (int j = 0; j < 8; ++j)
#pragma unroll
            for (int q = 0; q < 4; ++q) acc[i][j][q] = 0.f;

    // prologue: stages 0 and 1
    LOAD_STAGE(base);
    LOAD_STAGE(base + STAGE_B);

    for (int i = 0; i < niter; ++i) {
        if (i + 1 < niter) asm volatile("cp.async.wait_group 1;" ::: "memory");
        else               asm volatile("cp.async.wait_group 0;" ::: "memory");
        __syncthreads();

        if (i + 2 < niter) {
            int b2 = i + 2;
            b2 = b2 - (b2 / 3) * 3;          // (i+2) % 3
            LOAD_STAGE(base + b2 * STAGE_B);
        }

        int b0 = i - (i / 3) * 3;            // i % 3
        const uint32_t sb = base + b0 * STAGE_B;
        const uint32_t Ah = sb, Bh = sb + TILE_A;

#pragma unroll
        for (int ks = 0; ks < 4; ++ks) {
            uint32_t ah[2][4], bh[4][4];
            int ck = 2 * ks + hi4;
#pragma unroll
            for (int mt = 0; mt < 2; ++mt) {
                int row = wm * 32 + mt * 16 + r15;
                ldsm_x4(ah[mt], Ah + swz(row, ck));
            }
#pragma unroll
            for (int np = 0; np < 4; ++np) {
                int row = wn * 64 + np * 16 + r15;
                ldsm_x4(bh[np], Bh + swz(row, ck));
            }
#pragma unroll
            for (int mt = 0; mt < 2; ++mt)
#pragma unroll
                for (int nt = 0; nt < 8; ++nt) {
                    int np = nt >> 1, p = nt & 1;
                    mma16816(acc[mt][nt], ah[mt], bh[np][p], bh[np][p + 2]);
                }
        }
    }

    // epilogue: gram -> fp32 partials; forward -> fp16 activations
    if (sg.gram) {
        float* C = (float*)sg.C + (long)zoff * sg.pstride;
#pragma unroll
        for (int mt = 0; mt < 2; ++mt) {
            int row = m0 + wm * 32 + mt * 16 + (lane >> 2);
#pragma unroll
            for (int nt = 0; nt < 8; ++nt) {
                int col = n0 + wn * 64 + nt * 8 + 2 * (lane & 3);
                *(float2*)&C[(long)row * DD + col] = make_float2(acc[mt][nt][0], acc[mt][nt][1]);
                *(float2*)&C[(long)(row + 8) * DD + col] = make_float2(acc[mt][nt][2], acc[mt][nt][3]);
            }
        }
    } else {
        fp16* C = (fp16*)sg.C;
#pragma unroll
        for (int mt = 0; mt < 2; ++mt) {
            int row = m0 + wm * 32 + mt * 16 + (lane >> 2);
#pragma unroll
            for (int nt = 0; nt < 8; ++nt) {
                int col = n0 + wn * 64 + nt * 8 + 2 * (lane & 3);
                *(uint32_t*)&C[(long)row * DD + col] = pack2f(acc[mt][nt][0], acc[mt][nt][1]);
                *(uint32_t*)&C[(long)(row + 8) * DD + col] = pack2f(acc[mt][nt][2], acc[mt][nt][3]);
            }
        }
    }
#undef LOAD_STAGE
}

// ------- prep: coalesced fp16 quantize, row-major + transposed, packed stores -------
__global__ __launch_bounds__(256) void prep_big(const float* __restrict__ X,
                                                uint32_t* __restrict__ Hr,
                                                uint32_t* __restrict__ Th,
                                                int R, int C) {
    __shared__ float s[64][65];
    const int tid = threadIdx.x;
    const int c0 = blockIdx.x * 64, r0 = blockIdx.y * 64;

#pragma unroll
    for (int k = 0; k < 8; ++k) {
        int u = tid + k * 256;
        int rl = u >> 5, c2 = (u & 31) * 2;
        long ga = (long)(r0 + rl) * C + c0 + c2;
        float2 v = *(const float2*)&X[ga];
        Hr[ga >> 1] = pack2f(v.x, v.y);
        s[c2][rl] = v.x;
        s[c2 + 1][rl] = v.y;
    }
    __syncthreads();
#pragma unroll
    for (int k = 0; k < 8; ++k) {
        int u = tid + k * 256;
        int fl = u >> 5, r2 = (u & 31) * 2;
        long ta = (long)(c0 + fl) * R + r0 + r2;
        Th[ta >> 1] = pack2f(s[fl][r2], s[fl][r2 + 1]);
    }
}

// ------- prep for weights: transposed fp16 quantize, W and Wr via grid.z -------
__global__ __launch_bounds__(256) void prep_w(const float* __restrict__ W0,
                                              const float* __restrict__ W1,
                                              uint32_t* __restrict__ T0h,
                                              uint32_t* __restrict__ T1h) {
    __shared__ float s[64][65];
    const int tid = threadIdx.x;
    const int c0 = blockIdx.x * 64, r0 = blockIdx.y * 64;
    const float* X = blockIdx.z ? W1 : W0;
    uint32_t* Th = blockIdx.z ? T1h : T0h;

#pragma unroll
    for (int k = 0; k < 8; ++k) {
        int u = tid + k * 256;
        int rl = u >> 5, c2 = (u & 31) * 2;
        float2 v = *(const float2*)&X[(long)(r0 + rl) * DD + c0 + c2];
        s[c2][rl] = v.x;
        s[c2 + 1][rl] = v.y;
    }
    __syncthreads();
#pragma unroll
    for (int k = 0; k < 8; ++k) {
        int u = tid + k * 256;
        int fl = u >> 5, r2 = (u & 31) * 2;
        long ta = (long)(c0 + fl) * DD + r0 + r2;
        Th[ta >> 1] = pack2f(s[fl][r2], s[fl][r2 + 1]);
    }
}

// ------- warp-per-row fused LN(rec) -> add stim -> relu -> LN(act), fp16 inputs -------
__global__ __launch_bounds__(256) void ln_fuse(const __half2* __restrict__ rec2,
                                               const __half2* __restrict__ stim2,
                                               const float* __restrict__ grec,
                                               const float* __restrict__ brec,
                                               const float* __restrict__ gact,
                                               const float* __restrict__ bact,
                                               float* __restrict__ out) {
    const int lane = threadIdx.x & 31;
    const long row = (long)blockIdx.x * 8 + (threadIdx.x >> 5);
    const __half2* rr = rec2 + row * (DD / 2);
    const __half2* sr = stim2 + row * (DD / 2);
    float* orow = out + row * DD;

    // lane handles half2 index e*32 + lane (cols 2*(e*32+lane), +1)
    float2 x[8];
    float a = 0.f, bsum = 0.f;
#pragma unroll
    for (int e = 0; e < 8; ++e) {
        x[e] = __half22float2(rr[e * 32 + lane]);
        a += x[e].x + x[e].y;
        bsum += x[e].x * x[e].x + x[e].y * x[e].y;
    }
#pragma unroll
    for (int o = 16; o; o >>= 1) {
        a += __shfl_xor_sync(0xffffffffu, a, o);
        bsum += __shfl_xor_sync(0xffffffffu, bsum, o);
    }
    float mu = a * (1.f / DD);
    float var = bsum * (1.f / DD) - mu * mu;
    float rstd = rsqrtf(var + 1e-5f);

    float2 v[8];
    a = 0.f; bsum = 0.f;
#pragma unroll
    for (int e = 0; e < 8; ++e) {
        int c = 2 * (e * 32 + lane);
        float2 sv = __half22float2(sr[e * 32 + lane]);
        float rn0 = (x[e].x - mu) * rstd * grec[c] + brec[c];
        float rn1 = (x[e].y - mu) * rstd * grec[c + 1] + brec[c + 1];
        v[e].x = fmaxf(sv.x + rn0, 0.f);
        v[e].y = fmaxf(sv.y + rn1, 0.f);
        a += v[e].x + v[e].y;
        bsum += v[e].x * v[e].x + v[e].y * v[e].y;
    }
#pragma unroll
    for (int o = 16; o; o >>= 1) {
        a += __shfl_xor_sync(0xffffffffu, a, o);
        bsum += __shfl_xor_sync(0xffffffffu, bsum, o);
    }
    float mu2 = a * (1.f / DD);
    float var2 = bsum * (1.f / DD) - mu2 * mu2;
    float rstd2 = rsqrtf(var2 + 1e-5f);
#pragma unroll
    for (int e = 0; e < 8; ++e) {
        int c = 2 * (e * 32 + lane);
        float o0 = (v[e].x - mu2) * rstd2 * gact[c] + bact[c];
        float o1 = (v[e].y - mu2) * rstd2 * gact[c + 1] + bact[c + 1];
        *(float2*)&orow[c] = make_float2(o0, o1);
    }
}

// ---- weight update (fused gram reduction + symmetric mirror, 128-granular):
//      G = sum_z part[z], out = l2norm_rows(W*(1-decay_i) + alpha_j*(G@W)) ----
#define RPC 8
__global__ __launch_bounds__(512) void weight_update(const float* __restrict__ W0,
                                                     const float* __restrict__ partS,
                                                     const float* __restrict__ W1,
                                                     const float* __restrict__ partP,
                                                     const float* __restrict__ alpha,
                                                     const float* __restrict__ decay,
                                                     float* __restrict__ out0,
                                                     float* __restrict__ out1) {
    const float* Wm = blockIdx.y ? W1 : W0;
    const float* part = blockIdx.y ? partP : partS;
    float* outp = blockIdx.y ? out1 : out0;

    const int i0 = blockIdx.x * RPC;
    const int j = threadIdx.x;
    const int lane = j & 31;
    const int w = j >> 5;

    __shared__ float Gsm[RPC][DD];
    __shared__ float red[16];
    __shared__ float norms[RPC];

    // gram reduction with upper-tri mirror (128-block granular)
#pragma unroll
    for (int r = 0; r < RPC; ++r) {
        int i = i0 + r;
        size_t src = ((i >> 7) <= (j >> 7)) ? ((size_t)i * DD + j) : ((size_t)j * DD + i);
        float s = 0.f;
#pragma unroll
        for (int z = 0; z < NSPLIT; ++z) s += part[(size_t)z * DD * DD + src];
        Gsm[r][j] = s;
    }
    __syncthreads();

    float acc[RPC];
#pragma unroll
    for (int r = 0; r < RPC; ++r) acc[r] = 0.f;

#pragma unroll 4
    for (int k = 0; k < DD; ++k) {
        float wv = Wm[(size_t)k * DD + j];
#pragma unroll
        for (int r = 0; r < RPC; ++r) acc[r] = fmaf(Gsm[r][k], wv, acc[r]);
    }

    float aj = alpha[j];
#pragma unroll
    for (int r = 0; r < RPC; ++r)
        acc[r] = Wm[(size_t)(i0 + r) * DD + j] * (1.f - decay[i0 + r]) + aj * acc[r];

    for (int r = 0; r < RPC; ++r) {
        float s = acc[r] * acc[r];
#pragma unroll
        for (int o = 16; o; o >>= 1) s += __shfl_xor_sync(0xffffffffu, s, o);
        if (lane == 0) red[w] = s;
        __syncthreads();
        if (j == 0) {
            float tsum = 0.f;
#pragma unroll
            for (int q = 0; q < 16; ++q) tsum += red[q];
            norms[r] = fmaxf(sqrtf(tsum), 1e-12f);
        }
        __syncthreads();
    }

#pragma unroll
    for (int r = 0; r < RPC; ++r)
        outp[(size_t)(i0 + r) * DD + j] = acc[r] / norms[r];
}

// ---------------- launch ----------------
extern "C" void kernel_launch(void* const* d_in, const int* in_sizes, int n_in,
                              void* d_out, int out_size) {
    const float* stim = (const float*)d_in[0];
    const float* prev = (const float*)d_in[1];
    const float* W    = (const float*)d_in[2];
    const float* Wr   = (const float*)d_in[3];
    const float* alpha = (const float*)d_in[4];
    const float* decay = (const float*)d_in[5];
    const float* gact = (const float*)d_in[6];
    const float* bact = (const float*)d_in[7];
    const float* grec = (const float*)d_in[8];
    const float* brec = (const float*)d_in[9];
    float* out = (float*)d_out;

    const int Brows = in_sizes[0] / DD;  // 32768

    fp16 *s_hi, *p_hi, *st_hi, *pt_hi, *wt_hi, *wrt_hi, *stim_out, *rec_out;
    float *partS, *partP;
    cudaGetSymbolAddress((void**)&s_hi, g_s_hi);
    cudaGetSymbolAddress((void**)&p_hi, g_p_hi);
    cudaGetSymbolAddress((void**)&st_hi, g_st_hi);
    cudaGetSymbolAddress((void**)&pt_hi, g_pt_hi);
    cudaGetSymbolAddress((void**)&wt_hi, g_wt_hi);
    cudaGetSymbolAddress((void**)&wrt_hi, g_wrt_hi);
    cudaGetSymbolAddress((void**)&stim_out, g_stim_out);
    cudaGetSymbolAddress((void**)&rec_out, g_rec_out);
    cudaGetSymbolAddress((void**)&partS, g_partS);
    cudaGetSymbolAddress((void**)&partP, g_partP);

    cudaFuncSetAttribute(mma_all, cudaFuncAttributeMaxDynamicSharedMemorySize, SMEM_DYN);

    // launches 0-2: prep (mma_all stays at ncu capture index 3)
    prep_big<<<dim3(DD / 64, Brows / 64), 256>>>(stim, (uint32_t*)s_hi, (uint32_t*)st_hi, Brows, DD);
    prep_big<<<dim3(DD / 64, Brows / 64), 256>>>(prev, (uint32_t*)p_hi, (uint32_t*)pt_hi, Brows, DD);
    prep_w<<<dim3(DD / 64, DD / 64, 2), 256>>>(W, Wr, (uint32_t*)wt_hi, (uint32_t*)wrt_hi);

    // launch 3: ALL four GEMMs merged, gram blocks first (LPT order)
    const int fwdBlocks = (Brows / MT) * (DD / NT);   // 1024
    const int gramBlocks = 10 * NSPLIT;               // 80
    const int kcg = Brows / NSPLIT;                   // 4096
    Seg4 segs;
    segs.s[0] = {st_hi, st_hi, Brows, Brows, partS, DD * DD, kcg, 1, 0};
    segs.s[1] = {pt_hi, pt_hi, Brows, Brows, partP, DD * DD, kcg, 1, gramBlocks};
    segs.s[2] = {s_hi, wt_hi, DD, DD, stim_out, 0, DD, 0, 2 * gramBlocks};
    segs.s[3] = {p_hi, wrt_hi, DD, DD, rec_out, 0, DD, 0, 2 * gramBlocks + fwdBlocks};
    mma_all<<<2 * gramBlocks + 2 * fwdBlocks, 256, SMEM_DYN>>>(segs);

    ln_fuse<<<(unsigned)(Brows / 8), 256>>>((const __half2*)rec_out, (const __half2*)stim_out,
                                            grec, brec, gact, bact, out);

    size_t off = (size_t)Brows * DD;
    weight_update<<<dim3(DD / RPC, 2), 512>>>(W, partS, Wr, partP, alpha, decay,
                                              out + off, out + off + (size_t)DD * DD);
}

// round 15
// speedup vs baseline: 1.1875x; 1.0459x over previous
#include <cuda_runtime.h>
#include <cuda_fp16.h>
#include <cstdint>

typedef __half fp16;

// ---------------- problem constants ----------------
#define DD 512
#define MAXB 32768
#define NSPLIT 8
#define BKT 64                          // K per stage
#define MT 128
#define NT 128
#define TILE_A (MT * BKT * 2)           // 16384 B per operand tile
#define STAGE_B (2 * TILE_A)            // 32768 B (A, B)
#define NSTAGE 3
#define SMEM_DYN (NSTAGE * STAGE_B + 128)   // 98432 B -> 2 CTAs/SM

// ---------------- scratch (device globals; no allocation) ----------------
__device__ __align__(256) fp16 g_s_hi[(size_t)MAXB * DD];
__device__ __align__(256) fp16 g_p_hi[(size_t)MAXB * DD];
__device__ __align__(256) fp16 g_wt_hi[DD * DD];
__device__ __align__(256) fp16 g_wrt_hi[DD * DD];
__device__ __align__(256) fp16 g_stim_out[(size_t)MAXB * DD];
__device__ __align__(256) fp16 g_rec_out[(size_t)MAXB * DD];
__device__ __align__(256) float g_partS[(size_t)NSPLIT * DD * DD];
__device__ __align__(256) float g_partP[(size_t)NSPLIT * DD * DD];

// ---------------- PTX helpers (base-ISA only: sm_80+ safe) ----------------
__device__ __forceinline__ uint32_t smem_u32(const void* p) {
    uint32_t a;
    asm("{ .reg .u64 t; cvta.to.shared.u64 t, %1; cvt.u32.u64 %0, t; }" : "=r"(a) : "l"(p));
    return a;
}
__device__ __forceinline__ void ldsm_x4(uint32_t* r, uint32_t addr) {
    asm volatile("ldmatrix.sync.aligned.m8n8.x4.shared.b16 {%0,%1,%2,%3}, [%4];"
                 : "=r"(r[0]), "=r"(r[1]), "=r"(r[2]), "=r"(r[3]) : "r"(addr));
}
__device__ __forceinline__ void ldsm_x4_t(uint32_t* r, uint32_t addr) {
    asm volatile("ldmatrix.sync.aligned.m8n8.x4.trans.shared.b16 {%0,%1,%2,%3}, [%4];"
                 : "=r"(r[0]), "=r"(r[1]), "=r"(r[2]), "=r"(r[3]) : "r"(addr));
}
__device__ __forceinline__ void mma16816(float* c, const uint32_t* a, uint32_t b0, uint32_t b1) {
    asm volatile(
        "mma.sync.aligned.m16n8k16.row.col.f32.f16.f16.f32 "
        "{%0,%1,%2,%3}, {%4,%5,%6,%7}, {%8,%9}, {%0,%1,%2,%3};"
        : "+f"(c[0]), "+f"(c[1]), "+f"(c[2]), "+f"(c[3])
        : "r"(a[0]), "r"(a[1]), "r"(a[2]), "r"(a[3]), "r"(b0), "r"(b1));
}
__device__ __forceinline__ void cp16(uint32_t dst, const void* src) {
    asm volatile("cp.async.cg.shared.global [%0], [%1], 16;" :: "r"(dst), "l"(src) : "memory");
}
#define CP_COMMIT() asm volatile("cp.async.commit_group;" ::: "memory")

// forward-mode swizzle (128B rows, 8 chunks): chunk xor (row&7)
__device__ __forceinline__ uint32_t swz(int row, int chunk) {
    return (uint32_t)(row * 128 + ((chunk ^ (row & 7)) << 4));
}

__device__ __forceinline__ uint32_t pack2h(fp16 a, fp16 b) {
    return (uint32_t)__half_as_ushort(a) | ((uint32_t)__half_as_ushort(b) << 16);
}
__device__ __forceinline__ uint32_t pack2f(float a, float b) {
    return pack2h(__float2half(a), __float2half(b));
}

// ---------------- segment descriptor ----------------
struct Seg {
    const fp16 *Ah, *Bh;
    int lda, ldb;
    void* C;     // float* for gram partials, fp16* for forward outputs
    int pstride;
    int kc;
    int gram;    // 0: forward (A row-major 128B rows), 1: gram (operands from row-major X via trans-ldsm)
    int blk0;
};
struct Seg4 { Seg s[4]; };

// ---------------- merged single-pass fp16 GEMM ----------------
// forward: C[m,n] = sum_k A[m,k] B[n,k]   (A,B k-contiguous, 128B tile rows)
// gram:    C[i,j] = sum_b X[b,i] X[b,j]   (staged as 64 b-rows x 256B, trans-ldsm)
__global__ __launch_bounds__(256, 2)
void mma_all(Seg4 segs) {
    extern __shared__ char smraw[];
    const uint32_t base = (smem_u32(smraw) + 127u) & ~127u;

    const int bid = blockIdx.x;
    int si = (bid >= segs.s[2].blk0) ? ((bid >= segs.s[3].blk0) ? 3 : 2)
                                     : ((bid >= segs.s[1].blk0) ? 1 : 0);
    const Seg sg = segs.s[si];
    const int b = bid - sg.blk0;

    const int tid = threadIdx.x;
    const int lane = tid & 31;
    const int wid = tid >> 5;
    const int wm = wid >> 1;       // 4 warp-rows of 32
    const int wn = wid & 1;        // 2 warp-cols of 64
    const int r15 = lane & 15;
    const int hi4 = lane >> 4;

    float acc[2][8][4];
#pragma unroll
    for (int i = 0; i < 2; ++i)
#pragma unroll
        for (int j = 0; j < 8; ++j)
#pragma unroll
            for (int q = 0; q < 4; ++q) acc[i][j][q] = 0.f;

    if (!sg.gram) {
        // ================= forward path (R14 verbatim) =================
        const int m0 = (b >> 2) * MT;
        const int n0 = (b & 3) * NT;
        const int niter = sg.kc / BKT;

        const int rr = tid >> 3;
        const int cch = tid & 7;
        const uint32_t dA = (uint32_t)(rr * 128 + ((cch ^ (rr & 7)) << 4));
        const int offA = 32 * sg.lda;
        const int offB = 32 * sg.ldb;
        const fp16* pAh = sg.Ah + (m0 + rr) * sg.lda + cch * 8;
        const fp16* pBh = sg.Bh + (n0 + rr) * sg.ldb + cch * 8;

#define LOAD_STAGE_F(sbase) do {                                                \
    const uint32_t d0 = (sbase) + dA;                                           \
    _Pragma("unroll") for (int q = 0; q < 4; ++q)                               \
        cp16(d0 + q * 4096, pAh + q * offA);                                    \
    _Pragma("unroll") for (int q = 0; q < 4; ++q)                               \
        cp16(d0 + TILE_A + q * 4096, pBh + q * offB);                           \
    CP_COMMIT();                                                                \
    pAh += BKT; pBh += BKT;                                                     \
} while (0)

        LOAD_STAGE_F(base);
        LOAD_STAGE_F(base + STAGE_B);

        for (int i = 0; i < niter; ++i) {
            if (i + 1 < niter) asm volatile("cp.async.wait_group 1;" ::: "memory");
            else               asm volatile("cp.async.wait_group 0;" ::: "memory");
            __syncthreads();

            if (i + 2 < niter) {
                int b2 = i + 2; b2 = b2 - (b2 / 3) * 3;
                LOAD_STAGE_F(base + b2 * STAGE_B);
            }
            int b0 = i - (i / 3) * 3;
            const uint32_t sb = base + b0 * STAGE_B;
            const uint32_t Ah = sb, Bh = sb + TILE_A;

#pragma unroll
            for (int ks = 0; ks < 4; ++ks) {
                uint32_t ah[2][4], bh[4][4];
                int ck = 2 * ks + hi4;
#pragma unroll
                for (int mt = 0; mt < 2; ++mt) {
                    int row = wm * 32 + mt * 16 + r15;
                    ldsm_x4(ah[mt], Ah + swz(row, ck));
                }
#pragma unroll
                for (int np = 0; np < 4; ++np) {
                    int row = wn * 64 + np * 16 + r15;
                    ldsm_x4(bh[np], Bh + swz(row, ck));
                }
#pragma unroll
                for (int mt = 0; mt < 2; ++mt)
#pragma unroll
                    for (int nt = 0; nt < 8; ++nt) {
                        int np = nt >> 1, p = nt & 1;
                        mma16816(acc[mt][nt], ah[mt], bh[np][p], bh[np][p + 2]);
                    }
            }
        }
#undef LOAD_STAGE_F

        fp16* C = (fp16*)sg.C;
#pragma unroll
        for (int mt = 0; mt < 2; ++mt) {
            int row = m0 + wm * 32 + mt * 16 + (lane >> 2);
#pragma unroll
            for (int nt = 0; nt < 8; ++nt) {
                int col = n0 + wn * 64 + nt * 8 + 2 * (lane & 3);
                *(uint32_t*)&C[(long)row * DD + col] = pack2f(acc[mt][nt][0], acc[mt][nt][1]);
                *(uint32_t*)&C[(long)(row + 8) * DD + col] = pack2f(acc[mt][nt][2], acc[mt][nt][3]);
            }
        }
    } else {
        // ================= gram path (trans-ldsm from row-major X) =================
        const int PI[10] = {0, 0, 0, 0, 1, 1, 1, 2, 2, 3};
        const int PJ[10] = {0, 1, 2, 3, 1, 2, 3, 2, 3, 3};
        int p = b % 10, z = b / 10;
        const int m0 = PI[p] * MT;       // feature-i tile
        const int n0 = PJ[p] * NT;       // feature-j tile
        const int kbase = z * sg.kc;     // batch offset
        const int niter = sg.kc / BKT;

        // staging: tile = 64 batch-rows x 256B (128 fp16 features)
        const int krow = tid >> 4;       // 0..15 (rows advance by 16 per q)
        const int ch = tid & 15;         // 16B chunk within 256B row
        const uint32_t dG = (uint32_t)(krow * 256 + ((ch ^ (krow & 7)) << 4));
        const int offR = 16 * sg.lda;    // 16 batch rows per q
        const fp16* pA = sg.Ah + (kbase + krow) * sg.lda + m0 + ch * 8;
        const fp16* pB = sg.Bh + (kbase + krow) * sg.ldb + n0 + ch * 8;
        const int stepK = BKT * sg.lda;

#define LOAD_STAGE_G(sbase) do {                                                \
    const uint32_t d0 = (sbase) + dG;                                           \
    _Pragma("unroll") for (int q = 0; q < 4; ++q)                               \
        cp16(d0 + q * 4096, pA + q * offR);                                     \
    _Pragma("unroll") for (int q = 0; q < 4; ++q)                               \
        cp16(d0 + TILE_A + q * 4096, pB + q * offR);                            \
    CP_COMMIT();                                                                \
    pA += stepK; pB += stepK;                                                   \
} while (0)

        // per-lane trans-ldsm addressing: lane -> klane, chunk-offset, swizzle const
        const int klane = (lane & 7) + ((lane >> 4) << 3);   // 0..15
        const uint32_t rowbyte = (uint32_t)(klane * 256);
        const int sx = lane & 7;                             // = klane & 7
        const int coff = (lane & 8) >> 3;                    // chunk offset 0/1

        LOAD_STAGE_G(base);
        LOAD_STAGE_G(base + STAGE_B);

        for (int i = 0; i < niter; ++i) {
            if (i + 1 < niter) asm volatile("cp.async.wait_group 1;" ::: "memory");
            else               asm volatile("cp.async.wait_group 0;" ::: "memory");
            __syncthreads();

            if (i + 2 < niter) {
                int b2 = i + 2; b2 = b2 - (b2 / 3) * 3;
                LOAD_STAGE_G(base + b2 * STAGE_B);
            }
            int b0 = i - (i / 3) * 3;
            const uint32_t sb = base + b0 * STAGE_B;
            const uint32_t Ah = sb, Bh = sb + TILE_A;

#pragma unroll
            for (int ks = 0; ks < 4; ++ks) {
                uint32_t ah[2][4], bh[4][4];
                const uint32_t kb = (uint32_t)(ks * 4096) + rowbyte;
#pragma unroll
                for (int mt = 0; mt < 2; ++mt) {
                    int cb = wm * 4 + mt * 2 + coff;
                    ldsm_x4_t(ah[mt], Ah + kb + (uint32_t)((cb ^ sx) << 4));
                }
#pragma unroll
                for (int np = 0; np < 4; ++np) {
                    int cb = wn * 8 + np * 2 + coff;
                    ldsm_x4_t(bh[np], Bh + kb + (uint32_t)((cb ^ sx) << 4));
                }
#pragma unroll
                for (int mt = 0; mt < 2; ++mt)
#pragma unroll
                    for (int nt = 0; nt < 8; ++nt) {
                        int np = nt >> 1, pq = nt & 1;
                        mma16816(acc[mt][nt], ah[mt], bh[np][pq], bh[np][pq + 2]);
                    }
            }
        }
#undef LOAD_STAGE_G

        float* C = (float*)sg.C + (long)z * sg.pstride;
#pragma unroll
        for (int mt = 0; mt < 2; ++mt) {
            int row = m0 + wm * 32 + mt * 16 + (lane >> 2);
#pragma unroll
            for (int nt = 0; nt < 8; ++nt) {
                int col = n0 + wn * 64 + nt * 8 + 2 * (lane & 3);
                *(float2*)&C[(long)row * DD + col] = make_float2(acc[mt][nt][0], acc[mt][nt][1]);
                *(float2*)&C[(long)(row + 8) * DD + col] = make_float2(acc[mt][nt][2], acc[mt][nt][3]);
            }
        }
    }
}

// ------- prep: pure streaming fp32 -> fp16 quantize (no transpose) -------
__global__ __launch_bounds__(256) void prep_q(const float4* __restrict__ X,
                                              uint2* __restrict__ H) {
    long i = (long)blockIdx.x * 256 + threadIdx.x;
    float4 v = X[i];
    H[i] = make_uint2(pack2f(v.x, v.y), pack2f(v.z, v.w));
}

// ------- prep for weights: transposed fp16 quantize, W and Wr via grid.z -------
__global__ __launch_bounds__(256) void prep_w(const float* __restrict__ W0,
                                              const float* __restrict__ W1,
                                              uint32_t* __restrict__ T0h,
                                              uint32_t* __restrict__ T1h) {
    __shared__ float s[64][65];
    const int tid = threadIdx.x;
    const int c0 = blockIdx.x * 64, r0 = blockIdx.y * 64;
    const float* X = blockIdx.z ? W1 : W0;
    uint32_t* Th = blockIdx.z ? T1h : T0h;

#pragma unroll
    for (int k = 0; k < 8; ++k) {
        int u = tid + k * 256;
        int rl = u >> 5, c2 = (u & 31) * 2;
        float2 v = *(const float2*)&X[(long)(r0 + rl) * DD + c0 + c2];
        s[c2][rl] = v.x;
        s[c2 + 1][rl] = v.y;
    }
    __syncthreads();
#pragma unroll
    for (int k = 0; k < 8; ++k) {
        int u = tid + k * 256;
        int fl = u >> 5, r2 = (u & 31) * 2;
        long ta = (long)(c0 + fl) * DD + r0 + r2;
        Th[ta >> 1] = pack2f(s[fl][r2], s[fl][r2 + 1]);
    }
}

// ------- warp-per-row fused LN(rec) -> add stim -> relu -> LN(act), fp16 inputs -------
__global__ __launch_bounds__(256) void ln_fuse(const __half2* __restrict__ rec2,
                                               const __half2* __restrict__ stim2,
                                               const float* __restrict__ grec,
                                               const float* __restrict__ brec,
                                               const float* __restrict__ gact,
                                               const float* __restrict__ bact,
                                               float* __restrict__ out) {
    const int lane = threadIdx.x & 31;
    const long row = (long)blockIdx.x * 8 + (threadIdx.x >> 5);
    const __half2* rr = rec2 + row * (DD / 2);
    const __half2* sr = stim2 + row * (DD / 2);
    float* orow = out + row * DD;

    float2 x[8];
    float a = 0.f, bsum = 0.f;
#pragma unroll
    for (int e = 0; e < 8; ++e) {
        x[e] = __half22float2(rr[e * 32 + lane]);
        a += x[e].x + x[e].y;
        bsum += x[e].x * x[e].x + x[e].y * x[e].y;
    }
#pragma unroll
    for (int o = 16; o; o >>= 1) {
        a += __shfl_xor_sync(0xffffffffu, a, o);
        bsum += __shfl_xor_sync(0xffffffffu, bsum, o);
    }
    float mu = a * (1.f / DD);
    float var = bsum * (1.f / DD) - mu * mu;
    float rstd = rsqrtf(var + 1e-5f);

    float2 v[8];
    a = 0.f; bsum = 0.f;
#pragma unroll
    for (int e = 0; e < 8; ++e) {
        int c = 2 * (e * 32 + lane);
        float2 sv = __half22float2(sr[e * 32 + lane]);
        float rn0 = (x[e].x - mu) * rstd * grec[c] + brec[c];
        float rn1 = (x[e].y - mu) * rstd * grec[c + 1] + brec[c + 1];
        v[e].x = fmaxf(sv.x + rn0, 0.f);
        v[e].y = fmaxf(sv.y + rn1, 0.f);
        a += v[e].x + v[e].y;
        bsum += v[e].x * v[e].x + v[e].y * v[e].y;
    }
#pragma unroll
    for (int o = 16; o; o >>= 1) {
        a += __shfl_xor_sync(0xffffffffu, a, o);
        bsum += __shfl_xor_sync(0xffffffffu, bsum, o);
    }
    float mu2 = a * (1.f / DD);
    float var2 = bsum * (1.f / DD) - mu2 * mu2;
    float rstd2 = rsqrtf(var2 + 1e-5f);
#pragma unroll
    for (int e = 0; e < 8; ++e) {
        int c = 2 * (e * 32 + lane);
        float o0 = (v[e].x - mu2) * rstd2 * gact[c] + bact[c];
        float o1 = (v[e].y - mu2) * rstd2 * gact[c + 1] + bact[c + 1];
        *(float2*)&orow[c] = make_float2(o0, o1);
    }
}

// ---- weight update (fused gram reduction + symmetric mirror, 128-granular) ----
#define RPC 8
__global__ __launch_bounds__(512) void weight_update(const float* __restrict__ W0,
                                                     const float* __restrict__ partS,
                                                     const float* __restrict__ W1,
                                                     const float* __restrict__ partP,
                                                     const float* __restrict__ alpha,
                                                     const float* __restrict__ decay,
                                                     float* __restrict__ out0,
                                                     float* __restrict__ out1) {
    const float* Wm = blockIdx.y ? W1 : W0;
    const float* part = blockIdx.y ? partP : partS;
    float* outp = blockIdx.y ? out1 : out0;

    const int i0 = blockIdx.x * RPC;
    const int j = threadIdx.x;
    const int lane = j & 31;
    const int w = j >> 5;

    __shared__ float Gsm[RPC][DD];
    __shared__ float red[16];
    __shared__ float norms[RPC];

#pragma unroll
    for (int r = 0; r < RPC; ++r) {
        int i = i0 + r;
        size_t src = ((i >> 7) <= (j >> 7)) ? ((size_t)i * DD + j) : ((size_t)j * DD + i);
        float s = 0.f;
#pragma unroll
        for (int z = 0; z < NSPLIT; ++z) s += part[(size_t)z * DD * DD + src];
        Gsm[r][j] = s;
    }
    __syncthreads();

    float acc[RPC];
#pragma unroll
    for (int r = 0; r < RPC; ++r) acc[r] = 0.f;

#pragma unroll 4
    for (int k = 0; k < DD; ++k) {
        float wv = Wm[(size_t)k * DD + j];
#pragma unroll
        for (int r = 0; r < RPC; ++r) acc[r] = fmaf(Gsm[r][k], wv, acc[r]);
    }

    float aj = alpha[j];
#pragma unroll
    for (int r = 0; r < RPC; ++r)
        acc[r] = Wm[(size_t)(i0 + r) * DD + j] * (1.f - decay[i0 + r]) + aj * acc[r];

    for (int r = 0; r < RPC; ++r) {
        float s = acc[r] * acc[r];
#pragma unroll
        for (int o = 16; o; o >>= 1) s += __shfl_xor_sync(0xffffffffu, s, o);
        if (lane == 0) red[w] = s;
        __syncthreads();
        if (j == 0) {
            float tsum = 0.f;
#pragma unroll
            for (int q = 0; q < 16; ++q) tsum += red[q];
            norms[r] = fmaxf(sqrtf(tsum), 1e-12f);
        }
        __syncthreads();
    }

#pragma unroll
    for (int r = 0; r < RPC; ++r)
        outp[(size_t)(i0 + r) * DD + j] = acc[r] / norms[r];
}

// ---------------- launch ----------------
extern "C" void kernel_launch(void* const* d_in, const int* in_sizes, int n_in,
                              void* d_out, int out_size) {
    const float* stim = (const float*)d_in[0];
    const float* prev = (const float*)d_in[1];
    const float* W    = (const float*)d_in[2];
    const float* Wr   = (const float*)d_in[3];
    const float* alpha = (const float*)d_in[4];
    const float* decay = (const float*)d_in[5];
    const float* gact = (const float*)d_in[6];
    const float* bact = (const float*)d_in[7];
    const float* grec = (const float*)d_in[8];
    const float* brec = (const float*)d_in[9];
    float* out = (float*)d_out;

    const int Brows = in_sizes[0] / DD;  // 32768

    fp16 *s_hi, *p_hi, *wt_hi, *wrt_hi, *stim_out, *rec_out;
    float *partS, *partP;
    cudaGetSymbolAddress((void**)&s_hi, g_s_hi);
    cudaGetSymbolAddress((void**)&p_hi, g_p_hi);
    cudaGetSymbolAddress((void**)&wt_hi, g_wt_hi);
    cudaGetSymbolAddress((void**)&wrt_hi, g_wrt_hi);
    cudaGetSymbolAddress((void**)&stim_out, g_stim_out);
    cudaGetSymbolAddress((void**)&rec_out, g_rec_out);
    cudaGetSymbolAddress((void**)&partS, g_partS);
    cudaGetSymbolAddress((void**)&partP, g_partP);

    cudaFuncSetAttribute(mma_all, cudaFuncAttributeMaxDynamicSharedMemorySize, SMEM_DYN);

    // launches 0-2: prep (mma_all stays at ncu capture index 3)
    const int nv4 = Brows * DD / 4;
    prep_q<<<nv4 / 256, 256>>>((const float4*)stim, (uint2*)s_hi);
    prep_q<<<nv4 / 256, 256>>>((const float4*)prev, (uint2*)p_hi);
    prep_w<<<dim3(DD / 64, DD / 64, 2), 256>>>(W, Wr, (uint32_t*)wt_hi, (uint32_t*)wrt_hi);

    // launch 3: ALL four GEMMs merged, gram blocks first (LPT order)
    const int fwdBlocks = (Brows / MT) * (DD / NT);   // 1024
    const int gramBlocks = 10 * NSPLIT;               // 80
    const int kcg = Brows / NSPLIT;                   // 4096
    Seg4 segs;
    segs.s[0] = {s_hi, s_hi, DD, DD, partS, DD * DD, kcg, 1, 0};
    segs.s[1] = {p_hi, p_hi, DD, DD, partP, DD * DD, kcg, 1, gramBlocks};
    segs.s[2] = {s_hi, wt_hi, DD, DD, stim_out, 0, DD, 0, 2 * gramBlocks};
    segs.s[3] = {p_hi, wrt_hi, DD, DD, rec_out, 0, DD, 0, 2 * gramBlocks + fwdBlocks};
    mma_all<<<2 * gramBlocks + 2 * fwdBlocks, 256, SMEM_DYN>>>(segs);

    ln_fuse<<<(unsigned)(Brows / 8), 256>>>((const __half2*)rec_out, (const __half2*)stim_out,
                                            grec, brec, gact, bact, out);

    size_t off = (size_t)Brows * DD;
    weight_update<<<dim3(DD / RPC, 2), 512>>>(W, partS, Wr, partP, alpha, decay,
                                              out + off, out + off + (size_t)DD * DD);
}